// round 1
// baseline (speedup 1.0000x reference)
#include <cuda_runtime.h>
#include <cstdint>

#define NN   7680
#define NASM 256
#define CAPN 30
#define BSZ  64

// Precomputed reciprocal of column sums of the masked W_rec (W_enc denominator).
__device__ float g_inv_total[NN];

// ---------------------------------------------------------------------------
// Kernel A: col_total[j] = sum_i W_rec[i,j] over rows i whose assembly points
// to assembly j/CAPN. Then inv_total[j] = 1/max(total, 1e-6) — this is exactly
// the per-entry value of W_enc (since W_rec entries are 0/1).
// ---------------------------------------------------------------------------
__global__ void colsum_kernel(const int* __restrict__ p,
                              const float* __restrict__ W_rec) {
    int j = blockIdx.x * blockDim.x + threadIdx.x;
    if (j >= NN) return;
    int a = j / CAPN;
    float total = 0.f;
    for (int m = 0; m < NASM; ++m) {
        if (p[m] == a) {
            const float* row = W_rec + (size_t)m * CAPN * NN + j;
            #pragma unroll 6
            for (int r = 0; r < CAPN; ++r)
                total += row[(size_t)r * NN];
        }
    }
    g_inv_total[j] = 1.0f / fmaxf(total, 1e-6f);
}

// ---------------------------------------------------------------------------
// Stable top-30 selection matching jax.lax.top_k semantics:
// value descending, ties broken by ascending index.
// 30 rounds of block-wide argmax over the candidate columns
// (bases[] = list of assembly ids; candidates are their 30 columns each).
// Selected entries are marked with score = -1 (all valid scores are >= 0).
// ---------------------------------------------------------------------------
__device__ __forceinline__ void kwta_select(float* score,
                                            const int* bases, int nb,
                                            int* active,
                                            unsigned long long* wred,
                                            int tid) {
    int nel = nb * CAPN;
    for (int r = 0; r < CAPN; ++r) {
        unsigned long long best = 0ull;
        for (int e = tid; e < nel; e += 256) {
            int j = bases[e / CAPN] * CAPN + (e % CAPN);
            float v = score[j];
            if (v >= 0.f) {
                // score bits are monotone for v >= 0; +1 so v==0 beats "empty"
                unsigned long long key =
                    ((unsigned long long)(__float_as_uint(v) + 1u) << 32) |
                    (unsigned)(~j);
                if (key > best) best = key;
            }
        }
        #pragma unroll
        for (int o = 16; o > 0; o >>= 1) {
            unsigned long long oth = __shfl_down_sync(0xFFFFFFFFu, best, o);
            if (oth > best) best = oth;
        }
        if ((tid & 31) == 0) wred[tid >> 5] = best;
        __syncthreads();
        if (tid < 8) {
            unsigned long long v2 = wred[tid];
            #pragma unroll
            for (int o = 4; o > 0; o >>= 1) {
                unsigned long long oth = __shfl_down_sync(0xFFu, v2, o);
                if (oth > v2) v2 = oth;
            }
            if (tid == 0) {
                int j = (int)(~((unsigned)(v2 & 0xFFFFFFFFu)));
                active[r] = j;
                score[j] = -1.0f;   // remove from further rounds
            }
        }
        __syncthreads();
    }
}

// ---------------------------------------------------------------------------
// Kernel B: one block per sample. 256 threads.
// ---------------------------------------------------------------------------
__global__ __launch_bounds__(256)
void chase_kernel(const int* __restrict__ p,
                  const int* __restrict__ s,
                  const int* __restrict__ kk,
                  const float* __restrict__ W_in,
                  const float* __restrict__ W_rec,
                  float* __restrict__ out) {
    __shared__ float score[NN];           // 30 KB
    __shared__ int   p_sh[NASM];
    __shared__ int   active[CAPN];
    __shared__ int   bases[NASM + 1];
    __shared__ int   n_bases;
    __shared__ unsigned long long wred[8];
    __shared__ unsigned char targeted[NASM];
    __shared__ int   ov[NASM];
    __shared__ int   best_a;

    const int tid = threadIdx.x;
    const int b   = blockIdx.x;

    if (tid < NASM) p_sh[tid] = p[tid];
    __syncthreads();

    // ---- Step 1: score[j] = sum over 30 rows of W_in (assembly s[b]) ----
    {
        const float* Wbase = W_in + (size_t)(s[b] * CAPN) * NN;
        float acc[NN / 256];              // 30 regs
        #pragma unroll
        for (int c = 0; c < NN / 256; ++c) acc[c] = 0.f;
        for (int r = 0; r < CAPN; ++r) {
            const float* row = Wbase + (size_t)r * NN + tid;
            #pragma unroll
            for (int c = 0; c < NN / 256; ++c)
                acc[c] += row[c * 256];
        }
        #pragma unroll
        for (int c = 0; c < NN / 256; ++c)
            score[tid + c * 256] = acc[c];
    }
    if (tid < NASM) bases[tid] = tid;     // all assemblies are candidates
    if (tid == 0) n_bases = NASM;
    __syncthreads();

    kwta_select(score, bases, n_bases, active, wred, tid);

    // ---- Chase: run k[b] recurrent steps ----
    const int steps = kk[b];              // in [0, 8)
    for (int t = 0; t < steps; ++t) {
        // zero score + targeted flags
        #pragma unroll
        for (int c = 0; c < NN / 256; ++c) score[tid + c * 256] = 0.f;
        if (tid < NASM) targeted[tid] = 0;
        __syncthreads();

        if (tid < CAPN) {
            int i = active[tid];
            targeted[p_sh[i / CAPN]] = 1;
        }
        __syncthreads();

        // accumulate: each active neuron i contributes W_rec[i, a*30+c] * (1/total)
        // All contributions into a given column j are the SAME value
        // (1/total[j]) -> atomicAdd order doesn't affect the result.
        for (int e = tid; e < CAPN * CAPN; e += 256) {
            int i = active[e / CAPN];
            int c = e % CAPN;
            int a = p_sh[i / CAPN];
            int j = a * CAPN + c;
            float w = W_rec[(size_t)i * NN + j];
            if (w != 0.f) atomicAdd(&score[j], g_inv_total[j]);
        }

        // build candidate bases: targeted assemblies + smallest non-targeted
        // assembly (30 guaranteed-zero columns for zero-score tie filling)
        if (tid == 0) {
            int nb2 = 0;
            int fallback = -1;
            for (int a = 0; a < NASM; ++a) {
                if (targeted[a]) bases[nb2++] = a;
                else if (fallback < 0) fallback = a;
            }
            bases[nb2++] = fallback;
            n_bases = nb2;
        }
        __syncthreads();

        kwta_select(score, bases, n_bases, active, wred, tid);
    }

    // ---- Overlaps + argmax (first max wins) + one-hot output ----
    if (tid < NASM) ov[tid] = 0;
    __syncthreads();
    if (tid < CAPN) atomicAdd(&ov[active[tid] / CAPN], 1);
    __syncthreads();
    if (tid == 0) {
        int ba = 0, bv = ov[0];
        for (int a = 1; a < NASM; ++a)
            if (ov[a] > bv) { bv = ov[a]; ba = a; }
        best_a = ba;
    }
    __syncthreads();
    if (tid < NASM)
        out[b * NASM + tid] = (tid == best_a) ? 1.0f : 0.0f;
}

// ---------------------------------------------------------------------------
extern "C" void kernel_launch(void* const* d_in, const int* in_sizes, int n_in,
                              void* d_out, int out_size) {
    const int*   p     = (const int*)d_in[0];   // [256]
    const int*   s     = (const int*)d_in[1];   // [64]
    const int*   kk    = (const int*)d_in[2];   // [64]
    const float* W_in  = (const float*)d_in[3]; // [7680,7680]
    const float* W_rec = (const float*)d_in[4]; // [7680,7680]
    float* out = (float*)d_out;                 // [64,256]

    colsum_kernel<<<(NN + 255) / 256, 256>>>(p, W_rec);
    chase_kernel<<<BSZ, 256>>>(p, s, kk, W_in, W_rec, out);
}

// round 2
// speedup vs baseline: 3.4045x; 3.4045x over previous
#include <cuda_runtime.h>
#include <cstdint>

#define NN    7680
#define NASM  256
#define CAPN  30
#define BSZ   64
#define NT    256
#define NCHUNK (NN/NT)   // 30

// Scratch (device globals — no allocation allowed)
__device__ float g_inv_total[NN];
__device__ float g_score[BSZ][NN];

// ---------------------------------------------------------------------------
// Block-wide inclusive scan of one int per thread (256 threads).
// wsum: shared int[8]. Ends with a barrier so it is immediately reusable.
// ---------------------------------------------------------------------------
__device__ __forceinline__ int block_scan_incl(int v, int* wsum, int tid) {
    int lane = tid & 31, w = tid >> 5;
    int x = v;
    #pragma unroll
    for (int off = 1; off < 32; off <<= 1) {
        int n = __shfl_up_sync(0xFFFFFFFFu, x, off);
        if (lane >= off) x += n;
    }
    if (lane == 31) wsum[w] = x;
    __syncthreads();
    if (tid < 8) {
        int y = wsum[tid];
        #pragma unroll
        for (int off = 1; off < 8; off <<= 1) {
            int n = __shfl_up_sync(0xFFu, y, off);
            if (tid >= off) y += n;
        }
        wsum[tid] = y;
    }
    __syncthreads();
    int r = x + (w ? wsum[w - 1] : 0);
    __syncthreads();
    return r;
}

// ---------------------------------------------------------------------------
// Exact stable top-30 (jax.lax.top_k semantics: value desc, ties -> low index)
// via 4-pass radix threshold search on the float bit pattern (monotone, v>=0).
// Ownership is contiguous: thread t owns slots [t*NP, t*NP+NP), slots map to
// ascending column index j, so equal-value rank order == ascending j.
// Writes the 30 selected column indices into active[].
// ---------------------------------------------------------------------------
template<int NP, bool DIRECT>
__device__ void select_top30(const float* score, const int* bases, int nc,
                             int* active, int* hist8, int* cumS, int* wsum,
                             int* shtmp, int tid) {
    unsigned pref = 0;
    int k_rem = 30;
    #pragma unroll
    for (int pass = 0; pass < 4; ++pass) {
        const int shift = 24 - pass * 8;
        // zero per-warp histograms (8 warps x 256 bins)
        for (int i = tid; i < 8 * 256; i += NT) hist8[i] = 0;
        __syncthreads();
        const unsigned pmask = (pass == 0) ? 0u : (0xFFFFFFFFu << (shift + 8));
        int* myh = hist8 + (tid >> 5) * 256;
        #pragma unroll
        for (int q = 0; q < NP; ++q) {
            int e = tid * NP + q;
            if (e < nc) {
                int j = DIRECT ? e : (bases[e / CAPN] * CAPN + (e % CAPN));
                unsigned u = __float_as_uint(score[j]);
                if ((u & pmask) == pref) atomicAdd(&myh[(u >> shift) & 0xFF], 1);
            }
        }
        __syncthreads();
        // total per bucket, reversed so an inclusive scan gives cum(>= bucket)
        int brev = 255 - tid;
        int tot = 0;
        #pragma unroll
        for (int w = 0; w < 8; ++w) tot += hist8[w * 256 + brev];
        int S = block_scan_incl(tot, wsum, tid);      // = count(bucket >= brev)
        cumS[tid] = S;
        __syncthreads();
        int Sprev = tid ? cumS[tid - 1] : 0;          // = count(bucket > brev)
        if (S >= k_rem && Sprev < k_rem) {            // exactly one thread
            shtmp[0] = brev;                          // threshold byte B
            shtmp[1] = Sprev;                         // # elems strictly above B
        }
        __syncthreads();
        pref |= ((unsigned)shtmp[0]) << shift;
        k_rem -= shtmp[1];
        __syncthreads();
    }
    const unsigned T = pref;
    const int need_eq = k_rem;          // how many index-smallest ties to take
    const int n_gt = 30 - k_rem;
    // counting pass
    int cgt = 0, ceq = 0;
    #pragma unroll
    for (int q = 0; q < NP; ++q) {
        int e = tid * NP + q;
        if (e < nc) {
            int j = DIRECT ? e : (bases[e / CAPN] * CAPN + (e % CAPN));
            unsigned u = __float_as_uint(score[j]);
            if (u > T) cgt++; else if (u == T) ceq++;
        }
    }
    int pack = (cgt << 16) | ceq;
    int excl = block_scan_incl(pack, wsum, tid) - pack;
    int gt_off = excl >> 16;
    int eq_off = excl & 0xFFFF;
    // emission pass
    #pragma unroll
    for (int q = 0; q < NP; ++q) {
        int e = tid * NP + q;
        if (e < nc) {
            int j = DIRECT ? e : (bases[e / CAPN] * CAPN + (e % CAPN));
            unsigned u = __float_as_uint(score[j]);
            if (u > T) {
                active[gt_off++] = j;
            } else if (u == T) {
                if (eq_off < need_eq) active[n_gt + eq_off] = j;
                eq_off++;
            }
        }
    }
    __syncthreads();
}

// ---------------------------------------------------------------------------
// Prep kernel, fused:
//   blocks [0, 30):    inv_total[j] = 1 / max(masked colsum of W_rec, 1e-6)
//   blocks [30, 1950): g_score[b][chunk] = sum of 30 W_in rows (assembly s[b])
// Both sums are over 0/1 values -> exact in fp32, order-independent.
// ---------------------------------------------------------------------------
__global__ __launch_bounds__(NT)
void prep_kernel(const int* __restrict__ p, const int* __restrict__ s,
                 const float* __restrict__ W_in,
                 const float* __restrict__ W_rec) {
    const int bid = blockIdx.x;
    const int tid = threadIdx.x;
    if (bid < NCHUNK) {
        int j = bid * NT + tid;
        int a = j / CAPN;
        float total = 0.f;
        for (int m = 0; m < NASM; ++m) {
            if (__ldg(&p[m]) == a) {
                const float* row = W_rec + (size_t)m * CAPN * NN + j;
                #pragma unroll
                for (int r = 0; r < CAPN; ++r) total += row[(size_t)r * NN];
            }
        }
        g_inv_total[j] = 1.0f / fmaxf(total, 1e-6f);
    } else {
        int r = bid - NCHUNK;
        int b = r / NCHUNK;
        int chunk = r % NCHUNK;
        int sb = __ldg(&s[b]);
        int j = chunk * NT + tid;
        const float* base = W_in + (size_t)sb * CAPN * NN + j;
        float acc = 0.f;
        #pragma unroll
        for (int rr = 0; rr < CAPN; ++rr) acc += base[(size_t)rr * NN];
        g_score[b][j] = acc;
    }
}

// ---------------------------------------------------------------------------
// Chase kernel: one block per sample.
// ---------------------------------------------------------------------------
__global__ __launch_bounds__(NT)
void chase_kernel(const int* __restrict__ p, const int* __restrict__ kk,
                  const float* __restrict__ W_rec,
                  float* __restrict__ out) {
    __shared__ float score[NN];          // 30 KB
    __shared__ int   hist8[8 * 256];     // 8 KB
    __shared__ int   cumS[NT];
    __shared__ int   wsum[8];
    __shared__ int   shtmp[2];
    __shared__ int   p_sh[NASM];
    __shared__ int   active[CAPN];
    __shared__ int   bases[NASM];
    __shared__ int   targeted[NASM];
    __shared__ int   fb_min, nb_sh;
    __shared__ int   ov[NASM];

    const int tid = threadIdx.x;
    const int b   = blockIdx.x;

    if (tid < NASM) p_sh[tid] = p[tid];
    #pragma unroll
    for (int c = 0; c < NCHUNK; ++c)
        score[tid + c * NT] = g_score[b][tid + c * NT];
    __syncthreads();

    // ---- first k-WTA over all 7680 columns ----
    select_top30<NCHUNK, true>(score, nullptr, NN, active,
                               hist8, cumS, wsum, shtmp, tid);

    // ---- k[b] pointer-chasing steps ----
    const int steps = kk[b];             // in [0, 8)
    for (int t = 0; t < steps; ++t) {
        if (tid < NASM) targeted[tid] = 0;
        if (tid == 0) fb_min = NASM;
        __syncthreads();
        if (tid < CAPN) targeted[p_sh[active[tid] / CAPN]] = 1;
        __syncthreads();
        if (tid < NASM && !targeted[tid]) atomicMin(&fb_min, tid);
        __syncthreads();
        // fallback = smallest non-targeted assembly: provides the index-
        // smallest guaranteed-zero columns for zero-score tie filling.
        if (tid == 0) targeted[fb_min] = 1;
        __syncthreads();
        // compact targeted assemblies -> ascending bases[]
        int flag = (tid < NASM) ? targeted[tid] : 0;
        int pos = block_scan_incl(flag, wsum, tid);
        if (flag) bases[pos - 1] = tid;
        if (tid == NT - 1) nb_sh = pos;
        __syncthreads();
        const int nb = nb_sh;
        const int nc = nb * CAPN;        // <= 31*30 = 930
        for (int e = tid; e < nc; e += NT)
            score[bases[e / CAPN] * CAPN + (e % CAPN)] = 0.f;
        __syncthreads();
        // sparse gather-accumulate: every add into column j is the SAME value
        // (1/total[j]), so the atomicAdd order cannot change the result.
        for (int e = tid; e < CAPN * CAPN; e += NT) {
            int i = active[e / CAPN];
            int j = p_sh[i / CAPN] * CAPN + (e % CAPN);
            if (W_rec[(size_t)i * NN + j] != 0.f)
                atomicAdd(&score[j], g_inv_total[j]);
        }
        __syncthreads();
        select_top30<4, false>(score, bases, nc, active,
                               hist8, cumS, wsum, shtmp, tid);
    }

    // ---- overlaps + first-max argmax + one-hot write ----
    if (tid < NASM) ov[tid] = 0;
    __syncthreads();
    if (tid < CAPN) atomicAdd(&ov[active[tid] / CAPN], 1);
    __syncthreads();
    int key = (ov[tid] << 8) | (NASM - 1 - tid);   // ties -> smallest assembly
    #pragma unroll
    for (int off = 16; off > 0; off >>= 1)
        key = max(key, __shfl_down_sync(0xFFFFFFFFu, key, off));
    if ((tid & 31) == 0) wsum[tid >> 5] = key;
    __syncthreads();
    if (tid == 0) {
        int m = wsum[0];
        #pragma unroll
        for (int w = 1; w < 8; ++w) m = max(m, wsum[w]);
        shtmp[0] = NASM - 1 - (m & 0xFF);
    }
    __syncthreads();
    out[b * NASM + tid] = (tid == shtmp[0]) ? 1.0f : 0.0f;
}

// ---------------------------------------------------------------------------
extern "C" void kernel_launch(void* const* d_in, const int* in_sizes, int n_in,
                              void* d_out, int out_size) {
    const int*   p     = (const int*)d_in[0];   // [256]
    const int*   s     = (const int*)d_in[1];   // [64]
    const int*   kk    = (const int*)d_in[2];   // [64]
    const float* W_in  = (const float*)d_in[3]; // [7680,7680]
    const float* W_rec = (const float*)d_in[4]; // [7680,7680]
    float* out = (float*)d_out;                 // [64,256]

    prep_kernel<<<NCHUNK + BSZ * NCHUNK, NT>>>(p, s, W_in, W_rec);
    chase_kernel<<<BSZ, NT>>>(p, kk, W_rec, out);
}